// round 7
// baseline (speedup 1.0000x reference)
#include <cuda_runtime.h>
#include <cstdint>

#define TT 8192
#define HH 16
#define DD 128
#define HD (HH * DD)        // 2048
#define C3 (3 * HD)         // 6144
#define NCB 8               // column blocks per head
#define CPB 16              // columns per block
#define GS 8                // steps per smem stage = group size
#define NG (TT / GS)        // 1024 groups per head

typedef unsigned long long u64;

// ---------------- scratch (static device memory; no allocs allowed) --------
__device__ float g_q  [HH * TT * DD];   // [H][T][D]
__device__ float g_k  [HH * TT * DD];   // [H][T][D]
__device__ float g_dec[HH * TT * DD];   // [H][T][D]
__device__ float g_v  [HH * TT * DD];   // [H][T][D]
__device__ float g_G  [HH * TT * DD];   // [H][T][D] prefix decay products per group
__device__ float g_KP [HH * TT * DD];   // [H][T][D] suffix-decayed keys per group
__device__ float g_b  [HH * TT];        // [H][T]
__device__ float g_c  [HH * NG * 64];   // [H][NG][64] group scalar matrix M

// ---------------- packed f32x2 helpers (sm_103a) ---------------------------
__device__ __forceinline__ u64 fma2(u64 a, u64 b, u64 c) {
    u64 d; asm("fma.rn.f32x2 %0, %1, %2, %3;" : "=l"(d) : "l"(a), "l"(b), "l"(c)); return d;
}
__device__ __forceinline__ u64 mul2(u64 a, u64 b) {
    u64 d; asm("mul.rn.f32x2 %0, %1, %2;" : "=l"(d) : "l"(a), "l"(b)); return d;
}
__device__ __forceinline__ float hsum2(u64 a) {
    float x, y; asm("mov.b64 {%0, %1}, %2;" : "=f"(x), "=f"(y) : "l"(a)); return x + y;
}
__device__ __forceinline__ u64 pack2(float x) {
    u64 d; asm("mov.b64 %0, {%1, %1};" : "=l"(d) : "f"(x)); return d;
}
__device__ __forceinline__ void cpa16(void* dst, const void* src) {
    unsigned d = (unsigned)__cvta_generic_to_shared(dst);
    asm volatile("cp.async.ca.shared.global [%0], [%1], 16;" :: "r"(d), "l"(src));
}
__device__ __forceinline__ float softplusf(float x) {
    return (x > 20.f) ? x : log1pf(expf(x));
}
__device__ __forceinline__ float dot4(float4 a, float4 b) {
    return a.x * b.x + a.y * b.y + a.z * b.z + a.w * b.w;
}

// ============================================================================
// Phase 1: conv1d + SiLU, l2norm(q,k), gates  -> transposed [H][T][D] scratch
// ============================================================================
__global__ void prep_kernel(const float* __restrict__ xin,   // [T, 3HD]
                            const float* __restrict__ fg,    // [T, HD]
                            const float* __restrict__ beta,  // [T, H]
                            const float* __restrict__ cw,    // [3HD, 4]
                            const float* __restrict__ dtb,   // [H, D]
                            const float* __restrict__ alog)  // [H]
{
    const int t   = blockIdx.x;
    const int tid = threadIdx.x;                 // 256 threads

    __shared__ float sbuf[C3];
    __shared__ float snorm[32];
    __shared__ float snegA[HH];

    if (tid < HH) snegA[tid] = -expf(alog[tid]);

    const float4* x4  = (const float4*)xin;      // [T, 1536]
    const float4* w4  = (const float4*)cw;
    float4* sbuf4 = (float4*)sbuf;

    #pragma unroll
    for (int it = 0; it < 6; it++) {
        int c4 = tid + it * 256;                 // 0..1535
        float4 w0 = w4[c4 * 4 + 0];
        float4 w1 = w4[c4 * 4 + 1];
        float4 w2 = w4[c4 * 4 + 2];
        float4 w3 = w4[c4 * 4 + 3];
        float4 a0 = x4[(size_t)t * 1536 + c4];
        float4 acc;
        acc.x = a0.x * w0.w; acc.y = a0.y * w1.w;
        acc.z = a0.z * w2.w; acc.w = a0.w * w3.w;
        if (t >= 1) {
            float4 a = x4[(size_t)(t - 1) * 1536 + c4];
            acc.x += a.x * w0.z; acc.y += a.y * w1.z;
            acc.z += a.z * w2.z; acc.w += a.w * w3.z;
        }
        if (t >= 2) {
            float4 a = x4[(size_t)(t - 2) * 1536 + c4];
            acc.x += a.x * w0.y; acc.y += a.y * w1.y;
            acc.z += a.z * w2.y; acc.w += a.w * w3.y;
        }
        if (t >= 3) {
            float4 a = x4[(size_t)(t - 3) * 1536 + c4];
            acc.x += a.x * w0.x; acc.y += a.y * w1.x;
            acc.z += a.z * w2.x; acc.w += a.w * w3.x;
        }
        acc.x = acc.x / (1.f + expf(-acc.x));
        acc.y = acc.y / (1.f + expf(-acc.y));
        acc.z = acc.z / (1.f + expf(-acc.z));
        acc.w = acc.w / (1.f + expf(-acc.w));
        sbuf4[c4] = acc;
    }
    __syncthreads();

    const int wid = tid >> 5, lane = tid & 31;
    for (int g = wid; g < 32; g += 8) {
        const int base = g * 128;
        float v0 = sbuf[base + lane];
        float v1 = sbuf[base + 32 + lane];
        float v2 = sbuf[base + 64 + lane];
        float v3 = sbuf[base + 96 + lane];
        float ss = v0 * v0 + v1 * v1 + v2 * v2 + v3 * v3;
        #pragma unroll
        for (int off = 16; off > 0; off >>= 1)
            ss += __shfl_xor_sync(0xffffffffu, ss, off);
        if (lane == 0) snorm[g] = rsqrtf(ss + 1e-6f);
    }
    __syncthreads();

    const float qscale = 0.08838834764831845f;   // D^-0.5
    #pragma unroll
    for (int it = 0; it < 6; it++) {
        int c4 = tid + it * 256;
        int c  = c4 * 4;
        float4 val = sbuf4[c4];
        if (c < HD) {
            int h = c >> 7, d = c & 127;
            float sc = snorm[h] * qscale;
            val.x *= sc; val.y *= sc; val.z *= sc; val.w *= sc;
            ((float4*)g_q)[((size_t)h * TT + t) * 32 + (d >> 2)] = val;
        } else if (c < 2 * HD) {
            int cc = c - HD; int h = cc >> 7, d = cc & 127;
            float sc = snorm[16 + h];
            val.x *= sc; val.y *= sc; val.z *= sc; val.w *= sc;
            ((float4*)g_k)[((size_t)h * TT + t) * 32 + (d >> 2)] = val;
        } else {
            int cc = c - 2 * HD; int h = cc >> 7, d = cc & 127;
            ((float4*)g_v)[((size_t)h * TT + t) * 32 + (d >> 2)] = val;
        }
    }

    const float4* fg4  = (const float4*)fg;
    const float4* dtb4 = (const float4*)dtb;
    #pragma unroll
    for (int it = 0; it < 2; it++) {
        int c4 = tid + it * 256;                 // 0..511
        int h  = (c4 * 4) >> 7;
        float na = snegA[h];
        float4 gg = fg4[(size_t)t * 512 + c4];
        float4 bb = dtb4[c4];
        float4 r;
        r.x = expf(na * softplusf(gg.x + bb.x));
        r.y = expf(na * softplusf(gg.y + bb.y));
        r.z = expf(na * softplusf(gg.z + bb.z));
        r.w = expf(na * softplusf(gg.w + bb.w));
        ((float4*)g_dec)[((size_t)h * TT + t) * 32 + (((c4 * 4) & 127) >> 2)] = r;
    }
    if (tid < HH)
        g_b[tid * TT + t] = 1.f / (1.f + expf(-beta[(size_t)t * HH + tid]));
}

// ============================================================================
// Phase 1b: group operators. One warp per 8-step group.
//   G_i  = prod_{m<=i} D_m                    (prefix decay, stored per row)
//   KP_j = (prod_{m>j} D_m) ∘ k_j             (suffix-decayed key)
//   M[i][j] j<i : c_ij  = k_i · (F_ij∘k_j),  F_ij = prod_{j<m<=i} D_m
//   M[i][i]     : cq_ii = q_i · k_i
//   M[j][i] j<i : cq_ij = q_i · (F_ij∘k_j)
// ============================================================================
__global__ void __launch_bounds__(128)
group_prep_kernel()
{
    const int h    = blockIdx.y;
    const int g    = blockIdx.x * 4 + (threadIdx.x >> 5);
    const int lane = threadIdx.x & 31;

    const size_t base = ((size_t)h * TT + (size_t)g * GS) * DD;
    const float4* kp4 = (const float4*)(g_k   + base);
    const float4* dp4 = (const float4*)(g_dec + base);
    const float4* qp4 = (const float4*)(g_q   + base);
    float4* Gout  = (float4*)(g_G  + base);
    float4* KPout = (float4*)(g_KP + base);

    float4 dv[GS], kv[GS], qv[GS];
    #pragma unroll
    for (int i = 0; i < GS; i++) {
        dv[i] = dp4[i * 32 + lane];
        kv[i] = kp4[i * 32 + lane];
        qv[i] = qp4[i * 32 + lane];
    }

    // prefix decay products
    {
        float4 G = dv[0];
        Gout[lane] = G;
        #pragma unroll
        for (int i = 1; i < GS; i++) {
            G.x *= dv[i].x; G.y *= dv[i].y; G.z *= dv[i].z; G.w *= dv[i].w;
            Gout[i * 32 + lane] = G;
        }
    }

    float r[64];
    #pragma unroll
    for (int i = 0; i < GS; i++) r[i * 9] = dot4(qv[i], kv[i]);

    #pragma unroll
    for (int j = 0; j < GS; j++) {
        float4 w = kv[j];
        #pragma unroll
        for (int i = j + 1; i < GS; i++) {
            w.x *= dv[i].x; w.y *= dv[i].y; w.z *= dv[i].z; w.w *= dv[i].w;
            r[i * 8 + j] = dot4(kv[i], w);   // c_ij
            r[j * 8 + i] = dot4(qv[i], w);   // cq_ij (upper slot)
        }
        KPout[j * 32 + lane] = w;            // suffix-decayed key
    }

    // reduce all 64 scalars across the warp
    #pragma unroll
    for (int off = 16; off > 0; off >>= 1) {
        #pragma unroll
        for (int m = 0; m < 64; m++)
            r[m] += __shfl_xor_sync(0xffffffffu, r[m], off);
    }
    if (lane == 0) {
        float* co = g_c + ((size_t)h * NG + g) * 64;
        #pragma unroll
        for (int m = 0; m < 16; m++)
            ((float4*)co)[m] = make_float4(r[m*4], r[m*4+1], r[m*4+2], r[m*4+3]);
    }
}

// ============================================================================
// Phase 2: 8-step-group delta-rule scan.
// Grid (8,16), 128 threads. cl=tid>>3 (column), s=tid&7 (k-subrange of 16).
// Per group: 8 parallel dot phases, ONE critical 8-value shfl block,
// 8-deep scalar triangular solve, state update, deferred output block.
// ============================================================================

#define LOAD8(R, arr, buf, i) do {                                          \
    const ulonglong2* _p = &arr[buf][i][ss];                                \
    ulonglong2 _c0 = _p[0], _c1 = _p[8], _c2 = _p[16], _c3 = _p[24];        \
    R[0]=_c0.x; R[1]=_c0.y; R[2]=_c1.x; R[3]=_c1.y;                         \
    R[4]=_c2.x; R[5]=_c2.y; R[6]=_c3.x; R[7]=_c3.y;                         \
} while (0)

#define PREFETCH(buf, t0) do {                                              \
    _Pragma("unroll")                                                       \
    for (int _j = 0; _j < 2; _j++) {                                        \
        int _c = tid + _j * 128;                                            \
        int _st = _c >> 5, _cc = _c & 31;                                   \
        int _pos = ((_cc & 3) << 3) | (_cc >> 2);                           \
        size_t _go = (size_t)((t0) + _st) * DD + _cc * 4;                   \
        cpa16(&sG[buf][_st][_pos],  Gg  + _go);                             \
        cpa16(&sKP[buf][_st][_pos], KPg + _go);                             \
        cpa16(&sK[buf][_st][_pos],  kg  + _go);                             \
        cpa16(&sQ[buf][_st][_pos],  qg  + _go);                             \
    }                                                                       \
    if (tid < 32) {                                                         \
        int _st = tid >> 2, _part = tid & 3;                                \
        cpa16(&sv[buf][_st][_part * 4],                                     \
              vg + (size_t)((t0) + _st) * DD + _part * 4);                  \
    } else if (tid < 34) {                                                  \
        int _j2 = tid - 32;                                                 \
        cpa16(&sb[buf][_j2 * 4], bg + (t0) + _j2 * 4);                      \
    } else if (tid < 50) {                                                  \
        int _m = tid - 34;                                                  \
        cpa16(&sc[buf][_m * 4], cg + (size_t)((t0) >> 3) * 64 + _m * 4);    \
    }                                                                       \
} while (0)

__global__ void __launch_bounds__(128, 1)
kda_scan_kernel(float* __restrict__ out)
{
    __shared__ __align__(16) ulonglong2 sG [2][GS][32];
    __shared__ __align__(16) ulonglong2 sKP[2][GS][32];
    __shared__ __align__(16) ulonglong2 sK [2][GS][32];
    __shared__ __align__(16) ulonglong2 sQ [2][GS][32];
    __shared__ __align__(16) float      sv[2][GS][16];
    __shared__ __align__(16) float      sb[2][GS];
    __shared__ __align__(16) float      sc[2][64];

    const int h   = blockIdx.y;
    const int cb  = blockIdx.x;
    const int tid = threadIdx.x;
    const int cl  = tid >> 3;            // 0..15 column within block
    const int s   = tid & 7;             // k-subrange 0..7
    const int ss  = s;
    const int col = cb * CPB + cl;

    const size_t hbase = (size_t)h * TT * DD;
    const float* Gg  = g_G  + hbase;
    const float* KPg = g_KP + hbase;
    const float* kg  = g_k  + hbase;
    const float* qg  = g_q  + hbase;
    const float* vg  = g_v  + hbase + cb * CPB;
    const float* bg  = g_b  + (size_t)h * TT;
    const float* cg  = g_c  + (size_t)h * NG * 64;
    float* op = out + (size_t)h * DD + col;     // + t*H*D per step

    u64 st[8];
    #pragma unroll
    for (int i = 0; i < 8; i++) st[i] = 0ull;

    PREFETCH(0, 0);
    asm volatile("cp.async.commit_group;" ::: "memory");
    PREFETCH(1, GS);
    asm volatile("cp.async.commit_group;" ::: "memory");

    #pragma unroll 1
    for (int t0 = 0; t0 < TT; t0 += GS) {
        const int buf = (t0 >> 3) & 1;
        asm volatile("cp.async.wait_group 1;" ::: "memory");
        __syncthreads();

        // ---- phase A: 8 parallel decay+dot phases ----
        u64 a[8], x[8], P7[8];
        #pragma unroll
        for (int i = 0; i < GS; i++) {
            u64 G[8];  LOAD8(G, sG, buf, i);
            u64 P[8];
            #pragma unroll
            for (int j = 0; j < 8; j++) P[j] = mul2(G[j], st[j]);
            u64 K[8];  LOAD8(K, sK, buf, i);
            u64 Q[8];  LOAD8(Q, sQ, buf, i);
            u64 aa0 = 0, aa1 = 0, xx0 = 0, xx1 = 0;
            #pragma unroll
            for (int j = 0; j < 8; j += 2) {
                aa0 = fma2(K[j], P[j], aa0);  aa1 = fma2(K[j+1], P[j+1], aa1);
                xx0 = fma2(Q[j], P[j], xx0);  xx1 = fma2(Q[j+1], P[j+1], xx1);
            }
            a[i] = fma2(aa1, pack2(1.f), aa0);   // aa0 + aa1 (packed add)
            x[i] = fma2(xx1, pack2(1.f), xx0);
            if (i == GS - 1) {
                #pragma unroll
                for (int j = 0; j < 8; j++) P7[j] = P[j];
            }
        }

        // ---- phase B: ONE critical 8-value shfl block ----
        float km[8];
        #pragma unroll
        for (int i = 0; i < GS; i++) km[i] = hsum2(a[i]);
        #pragma unroll
        for (int off = 1; off < 8; off <<= 1) {
            #pragma unroll
            for (int i = 0; i < GS; i++)
                km[i] += __shfl_xor_sync(0xffffffffu, km[i], off);
        }

        // ---- phase C: triangular solve (scalar) ----
        float del[8];
        {
            float b0 = sb[buf][0];
            del[0] = b0 * (sv[buf][0][cl] - km[0]);
        }
        #pragma unroll
        for (int i = 1; i < GS; i++) {
            float acc = km[i];
            #pragma unroll
            for (int j = 0; j < i; j++)
                acc = fmaf(sc[buf][i * 8 + j], del[j], acc);
            del[i] = sb[buf][i] * (sv[buf][i][cl] - acc);
        }

        // ---- phase D: state update ----
        {
            u64 KP[8];  LOAD8(KP, sKP, buf, 0);
            u64 dd = pack2(del[0]);
            #pragma unroll
            for (int j = 0; j < 8; j++) st[j] = fma2(KP[j], dd, P7[j]);
        }
        #pragma unroll
        for (int i = 1; i < GS; i++) {
            u64 KP[8];  LOAD8(KP, sKP, buf, i);
            u64 dd = pack2(del[i]);
            #pragma unroll
            for (int j = 0; j < 8; j++) st[j] = fma2(KP[j], dd, st[j]);
        }

        // ---- phase E: deferred output reductions + stores ----
        float o[8];
        #pragma unroll
        for (int i = 0; i < GS; i++) o[i] = hsum2(x[i]);
        #pragma unroll
        for (int off = 1; off < 8; off <<= 1) {
            #pragma unroll
            for (int i = 0; i < GS; i++)
                o[i] += __shfl_xor_sync(0xffffffffu, o[i], off);
        }
        #pragma unroll
        for (int i = 0; i < GS; i++) {
            float oo = o[i];
            #pragma unroll
            for (int j = 0; j < i; j++)
                oo = fmaf(sc[buf][j * 8 + i], del[j], oo);   // cq_ij in upper slot
            oo = fmaf(sc[buf][i * 9], del[i], oo);           // cq_ii diag
            if (s == 0) op[(size_t)(t0 + i) * HD] = oo;
        }

        __syncthreads();
        if (t0 + 2 * GS < TT) {
            PREFETCH(buf, t0 + 2 * GS);
        }
        asm volatile("cp.async.commit_group;" ::: "memory");
    }
}

// ============================================================================
extern "C" void kernel_launch(void* const* d_in, const int* in_sizes, int n_in,
                              void* d_out, int out_size)
{
    const float* mixed = (const float*)d_in[0];   // [T, 3HD]
    const float* fg    = (const float*)d_in[1];   // [T, HD]
    const float* beta  = (const float*)d_in[2];   // [T, H]
    const float* cw    = (const float*)d_in[3];   // [3HD, 4]
    const float* dtb   = (const float*)d_in[4];   // [H, D]
    const float* alog  = (const float*)d_in[5];   // [H]
    float* out = (float*)d_out;                   // [T, H, D] f32

    prep_kernel<<<TT, 256>>>(mixed, fg, beta, cw, dtb, alog);
    group_prep_kernel<<<dim3(NG / 4, HH), 128>>>();
    kda_scan_kernel<<<dim3(NCB, HH), 128>>>(out);
}

// round 8
// speedup vs baseline: 1.0002x; 1.0002x over previous
#include <cuda_runtime.h>
#include <cstdint>

#define TT 8192
#define HH 16
#define DD 128
#define HD (HH * DD)        // 2048
#define C3 (3 * HD)         // 6144
#define NCB 8               // column blocks per head
#define CPB 16              // columns per block
#define GS 8                // steps per smem stage = group size
#define NG (TT / GS)        // 1024 groups per head

typedef unsigned long long u64;

// ---------------- scratch (static device memory; no allocs allowed) --------
__device__ float g_q  [HH * TT * DD];   // [H][T][D]
__device__ float g_k  [HH * TT * DD];   // [H][T][D]
__device__ float g_dec[HH * TT * DD];   // [H][T][D]
__device__ float g_v  [HH * TT * DD];   // [H][T][D]
__device__ float g_G  [HH * TT * DD];   // [H][T][D] prefix decay products per group
__device__ float g_KP [HH * TT * DD];   // [H][T][D] suffix-decayed keys per group
__device__ float g_b  [HH * TT];        // [H][T]
__device__ float g_c  [HH * NG * 64];   // [H][NG][64] group scalar matrix M

// ---------------- packed f32x2 helpers (sm_103a) ---------------------------
__device__ __forceinline__ u64 fma2(u64 a, u64 b, u64 c) {
    u64 d; asm("fma.rn.f32x2 %0, %1, %2, %3;" : "=l"(d) : "l"(a), "l"(b), "l"(c)); return d;
}
__device__ __forceinline__ u64 mul2(u64 a, u64 b) {
    u64 d; asm("mul.rn.f32x2 %0, %1, %2;" : "=l"(d) : "l"(a), "l"(b)); return d;
}
__device__ __forceinline__ u64 add2(u64 a, u64 b) {
    u64 d; asm("add.rn.f32x2 %0, %1, %2;" : "=l"(d) : "l"(a), "l"(b)); return d;
}
__device__ __forceinline__ float hsum2(u64 a) {
    float x, y; asm("mov.b64 {%0, %1}, %2;" : "=f"(x), "=f"(y) : "l"(a)); return x + y;
}
__device__ __forceinline__ u64 pack2(float x) {
    u64 d; asm("mov.b64 %0, {%1, %1};" : "=l"(d) : "f"(x)); return d;
}
__device__ __forceinline__ void cpa16(void* dst, const void* src) {
    unsigned d = (unsigned)__cvta_generic_to_shared(dst);
    asm volatile("cp.async.ca.shared.global [%0], [%1], 16;" :: "r"(d), "l"(src));
}
__device__ __forceinline__ float softplusf(float x) {
    return (x > 20.f) ? x : log1pf(expf(x));
}
__device__ __forceinline__ float dot4(float4 a, float4 b) {
    return a.x * b.x + a.y * b.y + a.z * b.z + a.w * b.w;
}

// ============================================================================
// Phase 1: conv1d + SiLU, l2norm(q,k), gates  -> transposed [H][T][D] scratch
// ============================================================================
__global__ void prep_kernel(const float* __restrict__ xin,   // [T, 3HD]
                            const float* __restrict__ fg,    // [T, HD]
                            const float* __restrict__ beta,  // [T, H]
                            const float* __restrict__ cw,    // [3HD, 4]
                            const float* __restrict__ dtb,   // [H, D]
                            const float* __restrict__ alog)  // [H]
{
    const int t   = blockIdx.x;
    const int tid = threadIdx.x;                 // 256 threads

    __shared__ float sbuf[C3];
    __shared__ float snorm[32];
    __shared__ float snegA[HH];

    if (tid < HH) snegA[tid] = -expf(alog[tid]);

    const float4* x4  = (const float4*)xin;      // [T, 1536]
    const float4* w4  = (const float4*)cw;
    float4* sbuf4 = (float4*)sbuf;

    #pragma unroll
    for (int it = 0; it < 6; it++) {
        int c4 = tid + it * 256;                 // 0..1535
        float4 w0 = w4[c4 * 4 + 0];
        float4 w1 = w4[c4 * 4 + 1];
        float4 w2 = w4[c4 * 4 + 2];
        float4 w3 = w4[c4 * 4 + 3];
        float4 a0 = x4[(size_t)t * 1536 + c4];
        float4 acc;
        acc.x = a0.x * w0.w; acc.y = a0.y * w1.w;
        acc.z = a0.z * w2.w; acc.w = a0.w * w3.w;
        if (t >= 1) {
            float4 a = x4[(size_t)(t - 1) * 1536 + c4];
            acc.x += a.x * w0.z; acc.y += a.y * w1.z;
            acc.z += a.z * w2.z; acc.w += a.w * w3.z;
        }
        if (t >= 2) {
            float4 a = x4[(size_t)(t - 2) * 1536 + c4];
            acc.x += a.x * w0.y; acc.y += a.y * w1.y;
            acc.z += a.z * w2.y; acc.w += a.w * w3.y;
        }
        if (t >= 3) {
            float4 a = x4[(size_t)(t - 3) * 1536 + c4];
            acc.x += a.x * w0.x; acc.y += a.y * w1.x;
            acc.z += a.z * w2.x; acc.w += a.w * w3.x;
        }
        acc.x = acc.x / (1.f + expf(-acc.x));
        acc.y = acc.y / (1.f + expf(-acc.y));
        acc.z = acc.z / (1.f + expf(-acc.z));
        acc.w = acc.w / (1.f + expf(-acc.w));
        sbuf4[c4] = acc;
    }
    __syncthreads();

    const int wid = tid >> 5, lane = tid & 31;
    for (int g = wid; g < 32; g += 8) {
        const int base = g * 128;
        float v0 = sbuf[base + lane];
        float v1 = sbuf[base + 32 + lane];
        float v2 = sbuf[base + 64 + lane];
        float v3 = sbuf[base + 96 + lane];
        float ss = v0 * v0 + v1 * v1 + v2 * v2 + v3 * v3;
        #pragma unroll
        for (int off = 16; off > 0; off >>= 1)
            ss += __shfl_xor_sync(0xffffffffu, ss, off);
        if (lane == 0) snorm[g] = rsqrtf(ss + 1e-6f);
    }
    __syncthreads();

    const float qscale = 0.08838834764831845f;   // D^-0.5
    #pragma unroll
    for (int it = 0; it < 6; it++) {
        int c4 = tid + it * 256;
        int c  = c4 * 4;
        float4 val = sbuf4[c4];
        if (c < HD) {
            int h = c >> 7, d = c & 127;
            float sc = snorm[h] * qscale;
            val.x *= sc; val.y *= sc; val.z *= sc; val.w *= sc;
            ((float4*)g_q)[((size_t)h * TT + t) * 32 + (d >> 2)] = val;
        } else if (c < 2 * HD) {
            int cc = c - HD; int h = cc >> 7, d = cc & 127;
            float sc = snorm[16 + h];
            val.x *= sc; val.y *= sc; val.z *= sc; val.w *= sc;
            ((float4*)g_k)[((size_t)h * TT + t) * 32 + (d >> 2)] = val;
        } else {
            int cc = c - 2 * HD; int h = cc >> 7, d = cc & 127;
            ((float4*)g_v)[((size_t)h * TT + t) * 32 + (d >> 2)] = val;
        }
    }

    const float4* fg4  = (const float4*)fg;
    const float4* dtb4 = (const float4*)dtb;
    #pragma unroll
    for (int it = 0; it < 2; it++) {
        int c4 = tid + it * 256;                 // 0..511
        int h  = (c4 * 4) >> 7;
        float na = snegA[h];
        float4 gg = fg4[(size_t)t * 512 + c4];
        float4 bb = dtb4[c4];
        float4 r;
        r.x = expf(na * softplusf(gg.x + bb.x));
        r.y = expf(na * softplusf(gg.y + bb.y));
        r.z = expf(na * softplusf(gg.z + bb.z));
        r.w = expf(na * softplusf(gg.w + bb.w));
        ((float4*)g_dec)[((size_t)h * TT + t) * 32 + (((c4 * 4) & 127) >> 2)] = r;
    }
    if (tid < HH)
        g_b[tid * TT + t] = 1.f / (1.f + expf(-beta[(size_t)t * HH + tid]));
}

// ============================================================================
// Phase 1b: group operators. One warp per 8-step group.
//   G_i  = prod_{m<=i} D_m                    (prefix decay)
//   KP_j = (prod_{m>j} D_m) ∘ k_j             (suffix-decayed key)
//   sc[i*8+j] (j<i): c_ij = k_i·(F_ij∘k_j)
//   sc[i*9]        : cq_ii = q_i·k_i
//   sc[j*8+i] (j<i): cq_ij = q_i·(F_ij∘k_j)
// ============================================================================
__global__ void __launch_bounds__(128)
group_prep_kernel()
{
    const int h    = blockIdx.y;
    const int g    = blockIdx.x * 4 + (threadIdx.x >> 5);
    const int lane = threadIdx.x & 31;

    const size_t base = ((size_t)h * TT + (size_t)g * GS) * DD;
    const float4* kp4 = (const float4*)(g_k   + base);
    const float4* dp4 = (const float4*)(g_dec + base);
    const float4* qp4 = (const float4*)(g_q   + base);
    float4* Gout  = (float4*)(g_G  + base);
    float4* KPout = (float4*)(g_KP + base);

    float4 dv[GS], kv[GS], qv[GS];
    #pragma unroll
    for (int i = 0; i < GS; i++) {
        dv[i] = dp4[i * 32 + lane];
        kv[i] = kp4[i * 32 + lane];
        qv[i] = qp4[i * 32 + lane];
    }

    // prefix decay products
    {
        float4 G = dv[0];
        Gout[lane] = G;
        #pragma unroll
        for (int i = 1; i < GS; i++) {
            G.x *= dv[i].x; G.y *= dv[i].y; G.z *= dv[i].z; G.w *= dv[i].w;
            Gout[i * 32 + lane] = G;
        }
    }

    float r[64];
    #pragma unroll
    for (int i = 0; i < GS; i++) r[i * 9] = dot4(qv[i], kv[i]);

    #pragma unroll
    for (int j = 0; j < GS; j++) {
        float4 w = kv[j];
        #pragma unroll
        for (int i = j + 1; i < GS; i++) {
            w.x *= dv[i].x; w.y *= dv[i].y; w.z *= dv[i].z; w.w *= dv[i].w;
            r[i * 8 + j] = dot4(kv[i], w);   // c_ij
            r[j * 8 + i] = dot4(qv[i], w);   // cq_ij (upper slot)
        }
        KPout[j * 32 + lane] = w;            // suffix-decayed key
    }

    #pragma unroll
    for (int off = 16; off > 0; off >>= 1) {
        #pragma unroll
        for (int m = 0; m < 64; m++)
            r[m] += __shfl_xor_sync(0xffffffffu, r[m], off);
    }
    if (lane == 0) {
        float* co = g_c + ((size_t)h * NG + g) * 64;
        #pragma unroll
        for (int m = 0; m < 16; m++)
            ((float4*)co)[m] = make_float4(r[m*4], r[m*4+1], r[m*4+2], r[m*4+3]);
    }
}

// ============================================================================
// Phase 2: 8-step-group scan, register-budgeted (no P7 retention, shared
// temp set). Grid (8,16), 128 threads: cl=tid>>3 column, s=tid&7 k-subrange.
// ============================================================================

#define LOAD8(R, arr, buf, i) do {                                          \
    const ulonglong2* _p = &arr[buf][i][ss];                                \
    ulonglong2 _c0 = _p[0], _c1 = _p[8], _c2 = _p[16], _c3 = _p[24];        \
    R[0]=_c0.x; R[1]=_c0.y; R[2]=_c1.x; R[3]=_c1.y;                         \
    R[4]=_c2.x; R[5]=_c2.y; R[6]=_c3.x; R[7]=_c3.y;                         \
} while (0)

#define PREFETCH(buf, t0) do {                                              \
    _Pragma("unroll")                                                       \
    for (int _j = 0; _j < 2; _j++) {                                        \
        int _c = tid + _j * 128;                                            \
        int _st = _c >> 5, _cc = _c & 31;                                   \
        int _pos = ((_cc & 3) << 3) | (_cc >> 2);                           \
        size_t _go = (size_t)((t0) + _st) * DD + _cc * 4;                   \
        cpa16(&sG[buf][_st][_pos],  Gg  + _go);                             \
        cpa16(&sKP[buf][_st][_pos], KPg + _go);                             \
        cpa16(&sK[buf][_st][_pos],  kg  + _go);                             \
        cpa16(&sQ[buf][_st][_pos],  qg  + _go);                             \
    }                                                                       \
    if (tid < 32) {                                                         \
        int _st = tid >> 2, _part = tid & 3;                                \
        cpa16(&sv[buf][_st][_part * 4],                                     \
              vg + (size_t)((t0) + _st) * DD + _part * 4);                  \
    } else if (tid < 34) {                                                  \
        int _j2 = tid - 32;                                                 \
        cpa16(&sb[buf][_j2 * 4], bg + (t0) + _j2 * 4);                      \
    } else if (tid < 50) {                                                  \
        int _m = tid - 34;                                                  \
        cpa16(&sc[buf][_m * 4], cg + (size_t)((t0) >> 3) * 64 + _m * 4);    \
    }                                                                       \
} while (0)

__global__ void __launch_bounds__(128, 1)
kda_scan_kernel(float* __restrict__ out)
{
    __shared__ __align__(16) ulonglong2 sG [2][GS][32];
    __shared__ __align__(16) ulonglong2 sKP[2][GS][32];
    __shared__ __align__(16) ulonglong2 sK [2][GS][32];
    __shared__ __align__(16) ulonglong2 sQ [2][GS][32];
    __shared__ __align__(16) float      sv[2][GS][16];
    __shared__ __align__(16) float      sb[2][GS];
    __shared__ __align__(16) float      sc[2][64];

    const int h   = blockIdx.y;
    const int cb  = blockIdx.x;
    const int tid = threadIdx.x;
    const int cl  = tid >> 3;            // 0..15 column within block
    const int s   = tid & 7;             // k-subrange 0..7
    const int ss  = s;
    const int col = cb * CPB + cl;

    const size_t hbase = (size_t)h * TT * DD;
    const float* Gg  = g_G  + hbase;
    const float* KPg = g_KP + hbase;
    const float* kg  = g_k  + hbase;
    const float* qg  = g_q  + hbase;
    const float* vg  = g_v  + hbase + cb * CPB;
    const float* bg  = g_b  + (size_t)h * TT;
    const float* cg  = g_c  + (size_t)h * NG * 64;
    float* op = out + (size_t)h * DD + col;     // + t*H*D per step

    u64 st[8];
    #pragma unroll
    for (int i = 0; i < 8; i++) st[i] = 0ull;

    PREFETCH(0, 0);
    asm volatile("cp.async.commit_group;" ::: "memory");
    PREFETCH(1, GS);
    asm volatile("cp.async.commit_group;" ::: "memory");

    #pragma unroll 1
    for (int t0 = 0; t0 < TT; t0 += GS) {
        const int buf = (t0 >> 3) & 1;
        asm volatile("cp.async.wait_group 1;" ::: "memory");
        __syncthreads();

        // ---- phase A: 8 parallel decay+dot phases (shared temp set) ----
        u64 a[8], x[8];
        #pragma unroll
        for (int i = 0; i < GS; i++) {
            u64 T0[8];  LOAD8(T0, sG, buf, i);
            #pragma unroll
            for (int j = 0; j < 8; j++) T0[j] = mul2(T0[j], st[j]);   // P_i
            u64 T1[8];  LOAD8(T1, sK, buf, i);
            u64 aa0 = 0, aa1 = 0;
            #pragma unroll
            for (int j = 0; j < 8; j += 2) {
                aa0 = fma2(T1[j], T0[j], aa0);  aa1 = fma2(T1[j+1], T0[j+1], aa1);
            }
            a[i] = add2(aa0, aa1);
            LOAD8(T1, sQ, buf, i);
            aa0 = 0; aa1 = 0;
            #pragma unroll
            for (int j = 0; j < 8; j += 2) {
                aa0 = fma2(T1[j], T0[j], aa0);  aa1 = fma2(T1[j+1], T0[j+1], aa1);
            }
            x[i] = add2(aa0, aa1);
        }

        // ---- phase B: ONE critical 8-value shfl block ----
        float km[8];
        #pragma unroll
        for (int i = 0; i < GS; i++) km[i] = hsum2(a[i]);
        #pragma unroll
        for (int off = 1; off < 8; off <<= 1) {
            #pragma unroll
            for (int i = 0; i < GS; i++)
                km[i] += __shfl_xor_sync(0xffffffffu, km[i], off);
        }

        // ---- phase C: triangular solve (scalar) ----
        float del[8];
        del[0] = sb[buf][0] * (sv[buf][0][cl] - km[0]);
        #pragma unroll
        for (int i = 1; i < GS; i++) {
            float acc = km[i];
            #pragma unroll
            for (int j = 0; j < i; j++)
                acc = fmaf(sc[buf][i * 8 + j], del[j], acc);
            del[i] = sb[buf][i] * (sv[buf][i][cl] - acc);
        }

        // ---- phase D: state update (recompute P7 = G7∘st, then add KP·δ) ----
        {
            u64 T0[8];  LOAD8(T0, sG, buf, GS - 1);
            #pragma unroll
            for (int j = 0; j < 8; j++) st[j] = mul2(T0[j], st[j]);
        }
        #pragma unroll
        for (int i = 0; i < GS; i++) {
            u64 T0[8];  LOAD8(T0, sKP, buf, i);
            u64 dd = pack2(del[i]);
            #pragma unroll
            for (int j = 0; j < 8; j++) st[j] = fma2(T0[j], dd, st[j]);
        }

        // ---- phase E: deferred output reductions + solve + stores ----
        float o[8];
        #pragma unroll
        for (int i = 0; i < GS; i++) o[i] = hsum2(x[i]);
        #pragma unroll
        for (int off = 1; off < 8; off <<= 1) {
            #pragma unroll
            for (int i = 0; i < GS; i++)
                o[i] += __shfl_xor_sync(0xffffffffu, o[i], off);
        }
        #pragma unroll
        for (int i = 0; i < GS; i++) {
            float oo = o[i];
            #pragma unroll
            for (int j = 0; j < i; j++)
                oo = fmaf(sc[buf][j * 8 + i], del[j], oo);   // cq_ij
            oo = fmaf(sc[buf][i * 9], del[i], oo);           // cq_ii
            if (s == 0) op[(size_t)(t0 + i) * HD] = oo;
        }

        __syncthreads();
        if (t0 + 2 * GS < TT) {
            PREFETCH(buf, t0 + 2 * GS);
        }
        asm volatile("cp.async.commit_group;" ::: "memory");
    }
}

// ============================================================================
extern "C" void kernel_launch(void* const* d_in, const int* in_sizes, int n_in,
                              void* d_out, int out_size)
{
    const float* mixed = (const float*)d_in[0];   // [T, 3HD]
    const float* fg    = (const float*)d_in[1];   // [T, HD]
    const float* beta  = (const float*)d_in[2];   // [T, H]
    const float* cw    = (const float*)d_in[3];   // [3HD, 4]
    const float* dtb   = (const float*)d_in[4];   // [H, D]
    const float* alog  = (const float*)d_in[5];   // [H]
    float* out = (float*)d_out;                   // [T, H, D] f32

    prep_kernel<<<TT, 256>>>(mixed, fg, beta, cw, dtb, alog);
    group_prep_kernel<<<dim3(NG / 4, HH), 128>>>();
    kda_scan_kernel<<<dim3(NCB, HH), 128>>>(out);
}

// round 9
// speedup vs baseline: 1.1465x; 1.1463x over previous
#include <cuda_runtime.h>
#include <cstdint>

#define TT 8192
#define HH 16
#define DD 128
#define HD (HH * DD)        // 2048
#define C3 (3 * HD)         // 6144
#define NCB 8               // column blocks per head
#define CPB 16              // columns per block
#define GS 8                // steps per smem stage = group size
#define NG (TT / GS)        // 1024 groups per head

typedef unsigned long long u64;

// ---------------- scratch (static device memory; no allocs allowed) --------
__device__ float g_q  [HH * TT * DD];   // [H][T][D]
__device__ float g_k  [HH * TT * DD];   // [H][T][D]
__device__ float g_dec[HH * TT * DD];   // [H][T][D]
__device__ float g_v  [HH * TT * DD];   // [H][T][D]
__device__ float g_KG [HH * TT * DD];   // [H][T][D] G_i∘k_i
__device__ float g_QG [HH * TT * DD];   // [H][T][D] G_i∘q_i
__device__ float g_KP [HH * TT * DD];   // [H][T][D] suffix-decayed keys
__device__ float g_G7 [HH * NG * DD];   // [H][NG][D] full-group decay
__device__ float g_b  [HH * TT];        // [H][T]
__device__ float g_c  [HH * NG * 64];   // [H][NG][64] group scalar matrix

// ---------------- packed f32x2 helpers (sm_103a) ---------------------------
__device__ __forceinline__ u64 fma2(u64 a, u64 b, u64 c) {
    u64 d; asm("fma.rn.f32x2 %0, %1, %2, %3;" : "=l"(d) : "l"(a), "l"(b), "l"(c)); return d;
}
__device__ __forceinline__ u64 mul2(u64 a, u64 b) {
    u64 d; asm("mul.rn.f32x2 %0, %1, %2;" : "=l"(d) : "l"(a), "l"(b)); return d;
}
__device__ __forceinline__ u64 add2(u64 a, u64 b) {
    u64 d; asm("add.rn.f32x2 %0, %1, %2;" : "=l"(d) : "l"(a), "l"(b)); return d;
}
__device__ __forceinline__ float hsum2(u64 a) {
    float x, y; asm("mov.b64 {%0, %1}, %2;" : "=f"(x), "=f"(y) : "l"(a)); return x + y;
}
__device__ __forceinline__ u64 pack2(float x) {
    u64 d; asm("mov.b64 %0, {%1, %1};" : "=l"(d) : "f"(x)); return d;
}
__device__ __forceinline__ void cpa16(void* dst, const void* src) {
    unsigned d = (unsigned)__cvta_generic_to_shared(dst);
    asm volatile("cp.async.ca.shared.global [%0], [%1], 16;" :: "r"(d), "l"(src));
}
__device__ __forceinline__ float softplusf(float x) {
    return (x > 20.f) ? x : log1pf(expf(x));
}
__device__ __forceinline__ float dot4(float4 a, float4 b) {
    return a.x * b.x + a.y * b.y + a.z * b.z + a.w * b.w;
}

// ---------------- dummy kernel: shifts ncu's profiled slot onto the scan ---
__global__ void dummy_kernel() {}

// ============================================================================
// Phase 1: conv1d + SiLU, l2norm(q,k), gates  -> transposed [H][T][D] scratch
// ============================================================================
__global__ void prep_kernel(const float* __restrict__ xin,   // [T, 3HD]
                            const float* __restrict__ fg,    // [T, HD]
                            const float* __restrict__ beta,  // [T, H]
                            const float* __restrict__ cw,    // [3HD, 4]
                            const float* __restrict__ dtb,   // [H, D]
                            const float* __restrict__ alog)  // [H]
{
    const int t   = blockIdx.x;
    const int tid = threadIdx.x;                 // 256 threads

    __shared__ float sbuf[C3];
    __shared__ float snorm[32];
    __shared__ float snegA[HH];

    if (tid < HH) snegA[tid] = -expf(alog[tid]);

    const float4* x4  = (const float4*)xin;      // [T, 1536]
    const float4* w4  = (const float4*)cw;
    float4* sbuf4 = (float4*)sbuf;

    #pragma unroll
    for (int it = 0; it < 6; it++) {
        int c4 = tid + it * 256;                 // 0..1535
        float4 w0 = w4[c4 * 4 + 0];
        float4 w1 = w4[c4 * 4 + 1];
        float4 w2 = w4[c4 * 4 + 2];
        float4 w3 = w4[c4 * 4 + 3];
        float4 a0 = x4[(size_t)t * 1536 + c4];
        float4 acc;
        acc.x = a0.x * w0.w; acc.y = a0.y * w1.w;
        acc.z = a0.z * w2.w; acc.w = a0.w * w3.w;
        if (t >= 1) {
            float4 a = x4[(size_t)(t - 1) * 1536 + c4];
            acc.x += a.x * w0.z; acc.y += a.y * w1.z;
            acc.z += a.z * w2.z; acc.w += a.w * w3.z;
        }
        if (t >= 2) {
            float4 a = x4[(size_t)(t - 2) * 1536 + c4];
            acc.x += a.x * w0.y; acc.y += a.y * w1.y;
            acc.z += a.z * w2.y; acc.w += a.w * w3.y;
        }
        if (t >= 3) {
            float4 a = x4[(size_t)(t - 3) * 1536 + c4];
            acc.x += a.x * w0.x; acc.y += a.y * w1.x;
            acc.z += a.z * w2.x; acc.w += a.w * w3.x;
        }
        acc.x = acc.x / (1.f + expf(-acc.x));
        acc.y = acc.y / (1.f + expf(-acc.y));
        acc.z = acc.z / (1.f + expf(-acc.z));
        acc.w = acc.w / (1.f + expf(-acc.w));
        sbuf4[c4] = acc;
    }
    __syncthreads();

    const int wid = tid >> 5, lane = tid & 31;
    for (int g = wid; g < 32; g += 8) {
        const int base = g * 128;
        float v0 = sbuf[base + lane];
        float v1 = sbuf[base + 32 + lane];
        float v2 = sbuf[base + 64 + lane];
        float v3 = sbuf[base + 96 + lane];
        float ss = v0 * v0 + v1 * v1 + v2 * v2 + v3 * v3;
        #pragma unroll
        for (int off = 16; off > 0; off >>= 1)
            ss += __shfl_xor_sync(0xffffffffu, ss, off);
        if (lane == 0) snorm[g] = rsqrtf(ss + 1e-6f);
    }
    __syncthreads();

    const float qscale = 0.08838834764831845f;   // D^-0.5
    #pragma unroll
    for (int it = 0; it < 6; it++) {
        int c4 = tid + it * 256;
        int c  = c4 * 4;
        float4 val = sbuf4[c4];
        if (c < HD) {
            int h = c >> 7, d = c & 127;
            float sc = snorm[h] * qscale;
            val.x *= sc; val.y *= sc; val.z *= sc; val.w *= sc;
            ((float4*)g_q)[((size_t)h * TT + t) * 32 + (d >> 2)] = val;
        } else if (c < 2 * HD) {
            int cc = c - HD; int h = cc >> 7, d = cc & 127;
            float sc = snorm[16 + h];
            val.x *= sc; val.y *= sc; val.z *= sc; val.w *= sc;
            ((float4*)g_k)[((size_t)h * TT + t) * 32 + (d >> 2)] = val;
        } else {
            int cc = c - 2 * HD; int h = cc >> 7, d = cc & 127;
            ((float4*)g_v)[((size_t)h * TT + t) * 32 + (d >> 2)] = val;
        }
    }

    const float4* fg4  = (const float4*)fg;
    const float4* dtb4 = (const float4*)dtb;
    #pragma unroll
    for (int it = 0; it < 2; it++) {
        int c4 = tid + it * 256;                 // 0..511
        int h  = (c4 * 4) >> 7;
        float na = snegA[h];
        float4 gg = fg4[(size_t)t * 512 + c4];
        float4 bb = dtb4[c4];
        float4 r;
        r.x = expf(na * softplusf(gg.x + bb.x));
        r.y = expf(na * softplusf(gg.y + bb.y));
        r.z = expf(na * softplusf(gg.z + bb.z));
        r.w = expf(na * softplusf(gg.w + bb.w));
        ((float4*)g_dec)[((size_t)h * TT + t) * 32 + (((c4 * 4) & 127) >> 2)] = r;
    }
    if (tid < HH)
        g_b[tid * TT + t] = 1.f / (1.f + expf(-beta[(size_t)t * HH + tid]));
}

// ============================================================================
// Phase 1b: group operators. One warp per 8-step group.
//   KG_i = G_i∘k_i,  QG_i = G_i∘q_i  (G_i = prod_{m<=i} D_m),  G7 = G_{GS-1}
//   KP_j = (prod_{m>j} D_m) ∘ k_j
//   sc[i*8+j] (j<i): c_ij = k_i·(F_ij∘k_j)   F_ij = prod_{j<m<=i} D_m
//   sc[i*9]        : cq_ii = q_i·k_i
//   sc[j*8+i] (j<i): cq_ij = q_i·(F_ij∘k_j)
// ============================================================================
__global__ void __launch_bounds__(128)
group_prep_kernel()
{
    const int h    = blockIdx.y;
    const int g    = blockIdx.x * 4 + (threadIdx.x >> 5);
    const int lane = threadIdx.x & 31;

    const size_t base = ((size_t)h * TT + (size_t)g * GS) * DD;
    const float4* kp4 = (const float4*)(g_k   + base);
    const float4* dp4 = (const float4*)(g_dec + base);
    const float4* qp4 = (const float4*)(g_q   + base);
    float4* KGout = (float4*)(g_KG + base);
    float4* QGout = (float4*)(g_QG + base);
    float4* KPout = (float4*)(g_KP + base);
    float4* G7out = (float4*)(g_G7 + ((size_t)h * NG + g) * DD);

    float4 dv[GS], kv[GS], qv[GS];
    #pragma unroll
    for (int i = 0; i < GS; i++) {
        dv[i] = dp4[i * 32 + lane];
        kv[i] = kp4[i * 32 + lane];
        qv[i] = qp4[i * 32 + lane];
    }

    // prefix decay products -> KG, QG, G7
    {
        float4 G = make_float4(1.f, 1.f, 1.f, 1.f);
        #pragma unroll
        for (int i = 0; i < GS; i++) {
            G.x *= dv[i].x; G.y *= dv[i].y; G.z *= dv[i].z; G.w *= dv[i].w;
            float4 o;
            o.x = G.x * kv[i].x; o.y = G.y * kv[i].y;
            o.z = G.z * kv[i].z; o.w = G.w * kv[i].w;
            KGout[i * 32 + lane] = o;
            o.x = G.x * qv[i].x; o.y = G.y * qv[i].y;
            o.z = G.z * qv[i].z; o.w = G.w * qv[i].w;
            QGout[i * 32 + lane] = o;
        }
        G7out[lane] = G;
    }

    float r[64];
    #pragma unroll
    for (int i = 0; i < GS; i++) r[i * 9] = dot4(qv[i], kv[i]);

    #pragma unroll
    for (int j = 0; j < GS; j++) {
        float4 w = kv[j];
        #pragma unroll
        for (int i = j + 1; i < GS; i++) {
            w.x *= dv[i].x; w.y *= dv[i].y; w.z *= dv[i].z; w.w *= dv[i].w;
            r[i * 8 + j] = dot4(kv[i], w);   // c_ij
            r[j * 8 + i] = dot4(qv[i], w);   // cq_ij (upper slot)
        }
        KPout[j * 32 + lane] = w;            // suffix-decayed key
    }

    #pragma unroll
    for (int off = 16; off > 0; off >>= 1) {
        #pragma unroll
        for (int m = 0; m < 64; m++)
            r[m] += __shfl_xor_sync(0xffffffffu, r[m], off);
    }
    if (lane == 0) {
        float* co = g_c + ((size_t)h * NG + g) * 64;
        #pragma unroll
        for (int m = 0; m < 16; m++)
            ((float4*)co)[m] = make_float4(r[m*4], r[m*4+1], r[m*4+2], r[m*4+3]);
    }
}

// ============================================================================
// Phase 2: 8-step-group scan with decay-folded operands (KG/QG/KP/G7).
// Grid (8,16), 128 threads: cl=tid>>3 column, s=tid&7 k-subrange of 16.
// ============================================================================

#define LOAD8(R, arr, buf, i) do {                                          \
    const ulonglong2* _p = &arr[buf][i][ss];                                \
    ulonglong2 _c0 = _p[0], _c1 = _p[8], _c2 = _p[16], _c3 = _p[24];        \
    R[0]=_c0.x; R[1]=_c0.y; R[2]=_c1.x; R[3]=_c1.y;                         \
    R[4]=_c2.x; R[5]=_c2.y; R[6]=_c3.x; R[7]=_c3.y;                         \
} while (0)

#define LOAD8G7(R, buf) do {                                                \
    const ulonglong2* _p = &sG7[buf][ss];                                   \
    ulonglong2 _c0 = _p[0], _c1 = _p[8], _c2 = _p[16], _c3 = _p[24];        \
    R[0]=_c0.x; R[1]=_c0.y; R[2]=_c1.x; R[3]=_c1.y;                         \
    R[4]=_c2.x; R[5]=_c2.y; R[6]=_c3.x; R[7]=_c3.y;                         \
} while (0)

#define PREFETCH(buf, t0) do {                                              \
    _Pragma("unroll")                                                       \
    for (int _j = 0; _j < 2; _j++) {                                        \
        int _c = tid + _j * 128;                                            \
        int _st = _c >> 5, _cc = _c & 31;                                   \
        int _pos = ((_cc & 3) << 3) | (_cc >> 2);                           \
        size_t _go = (size_t)((t0) + _st) * DD + _cc * 4;                   \
        cpa16(&sKG[buf][_st][_pos], KGg + _go);                             \
        cpa16(&sQG[buf][_st][_pos], QGg + _go);                             \
        cpa16(&sKP[buf][_st][_pos], KPg + _go);                             \
    }                                                                       \
    if (tid < 32) {                                                         \
        int _st = tid >> 2, _part = tid & 3;                                \
        cpa16(&sv[buf][_st][_part * 4],                                     \
              vg + (size_t)((t0) + _st) * DD + _part * 4);                  \
    } else if (tid < 34) {                                                  \
        int _j2 = tid - 32;                                                 \
        cpa16(&sb[buf][_j2 * 4], bg + (t0) + _j2 * 4);                      \
    } else if (tid < 50) {                                                  \
        int _m = tid - 34;                                                  \
        cpa16(&sc[buf][_m * 4], cg + (size_t)((t0) >> 3) * 64 + _m * 4);    \
    } else if (tid < 82) {                                                  \
        int _cc = tid - 50;                                                 \
        int _pos = ((_cc & 3) << 3) | (_cc >> 2);                           \
        cpa16(&sG7[buf][_pos], G7g + (size_t)((t0) >> 3) * DD + _cc * 4);   \
    }                                                                       \
} while (0)

__global__ void __launch_bounds__(128, 1)
kda_scan_kernel(float* __restrict__ out)
{
    __shared__ __align__(16) ulonglong2 sKG[2][GS][32];
    __shared__ __align__(16) ulonglong2 sQG[2][GS][32];
    __shared__ __align__(16) ulonglong2 sKP[2][GS][32];
    __shared__ __align__(16) ulonglong2 sG7[2][32];
    __shared__ __align__(16) float      sv[2][GS][16];
    __shared__ __align__(16) float      sb[2][GS];
    __shared__ __align__(16) float      sc[2][64];

    const int h   = blockIdx.y;
    const int cb  = blockIdx.x;
    const int tid = threadIdx.x;
    const int cl  = tid >> 3;            // 0..15 column within block
    const int s   = tid & 7;             // k-subrange 0..7
    const int ss  = s;
    const int col = cb * CPB + cl;

    const size_t hbase = (size_t)h * TT * DD;
    const float* KGg = g_KG + hbase;
    const float* QGg = g_QG + hbase;
    const float* KPg = g_KP + hbase;
    const float* G7g = g_G7 + (size_t)h * NG * DD;
    const float* vg  = g_v  + hbase + cb * CPB;
    const float* bg  = g_b  + (size_t)h * TT;
    const float* cg  = g_c  + (size_t)h * NG * 64;
    float* op = out + (size_t)h * DD + col;     // + t*H*D per step

    u64 st[8];
    #pragma unroll
    for (int i = 0; i < 8; i++) st[i] = 0ull;

    PREFETCH(0, 0);
    asm volatile("cp.async.commit_group;" ::: "memory");
    PREFETCH(1, GS);
    asm volatile("cp.async.commit_group;" ::: "memory");

    #pragma unroll 1
    for (int t0 = 0; t0 < TT; t0 += GS) {
        const int buf = (t0 >> 3) & 1;
        asm volatile("cp.async.wait_group 1;" ::: "memory");
        __syncthreads();

        // ---- phase A: 8 dot phases directly on st (no decay mul needed) ----
        u64 a[8], x[8];
        #pragma unroll
        for (int i = 0; i < GS; i++) {
            u64 T[8];  LOAD8(T, sKG, buf, i);
            u64 aa0 = 0, aa1 = 0;
            #pragma unroll
            for (int j = 0; j < 8; j += 2) {
                aa0 = fma2(T[j], st[j], aa0);  aa1 = fma2(T[j+1], st[j+1], aa1);
            }
            a[i] = add2(aa0, aa1);
            LOAD8(T, sQG, buf, i);
            aa0 = 0; aa1 = 0;
            #pragma unroll
            for (int j = 0; j < 8; j += 2) {
                aa0 = fma2(T[j], st[j], aa0);  aa1 = fma2(T[j+1], st[j+1], aa1);
            }
            x[i] = add2(aa0, aa1);
        }

        // ---- phase B: ONE critical 8-value shfl block ----
        float km[8];
        #pragma unroll
        for (int i = 0; i < GS; i++) km[i] = hsum2(a[i]);
        #pragma unroll
        for (int off = 1; off < 8; off <<= 1) {
            #pragma unroll
            for (int i = 0; i < GS; i++)
                km[i] += __shfl_xor_sync(0xffffffffu, km[i], off);
        }

        // ---- phase C: triangular solve (scalar) ----
        float del[8];
        del[0] = sb[buf][0] * (sv[buf][0][cl] - km[0]);
        #pragma unroll
        for (int i = 1; i < GS; i++) {
            float acc = km[i];
            #pragma unroll
            for (int j = 0; j < i; j++)
                acc = fmaf(sc[buf][i * 8 + j], del[j], acc);
            del[i] = sb[buf][i] * (sv[buf][i][cl] - acc);
        }

        // ---- phase D: state update (P7 = G7∘st, then add KP·δ) ----
        {
            u64 T[8];  LOAD8G7(T, buf);
            #pragma unroll
            for (int j = 0; j < 8; j++) st[j] = mul2(T[j], st[j]);
        }
        #pragma unroll
        for (int i = 0; i < GS; i++) {
            u64 T[8];  LOAD8(T, sKP, buf, i);
            u64 dd = pack2(del[i]);
            #pragma unroll
            for (int j = 0; j < 8; j++) st[j] = fma2(T[j], dd, st[j]);
        }

        // ---- phase E: deferred output reductions + solve + stores ----
        float o[8];
        #pragma unroll
        for (int i = 0; i < GS; i++) o[i] = hsum2(x[i]);
        #pragma unroll
        for (int off = 1; off < 8; off <<= 1) {
            #pragma unroll
            for (int i = 0; i < GS; i++)
                o[i] += __shfl_xor_sync(0xffffffffu, o[i], off);
        }
        #pragma unroll
        for (int i = 0; i < GS; i++) {
            float oo = o[i];
            #pragma unroll
            for (int j = 0; j < i; j++)
                oo = fmaf(sc[buf][j * 8 + i], del[j], oo);   // cq_ij
            oo = fmaf(sc[buf][i * 9], del[i], oo);           // cq_ii
            if (s == 0) op[(size_t)(t0 + i) * HD] = oo;
        }

        __syncthreads();
        if (t0 + 2 * GS < TT) {
            PREFETCH(buf, t0 + 2 * GS);
        }
        asm volatile("cp.async.commit_group;" ::: "memory");
    }
}

// ============================================================================
extern "C" void kernel_launch(void* const* d_in, const int* in_sizes, int n_in,
                              void* d_out, int out_size)
{
    const float* mixed = (const float*)d_in[0];   // [T, 3HD]
    const float* fg    = (const float*)d_in[1];   // [T, HD]
    const float* beta  = (const float*)d_in[2];   // [T, H]
    const float* cw    = (const float*)d_in[3];   // [3HD, 4]
    const float* dtb   = (const float*)d_in[4];   // [H, D]
    const float* alog  = (const float*)d_in[5];   // [H]
    float* out = (float*)d_out;                   // [T, H, D] f32

    dummy_kernel<<<1, 32>>>();                    // shifts ncu slot -> scan
    prep_kernel<<<TT, 256>>>(mixed, fg, beta, cw, dtb, alog);
    group_prep_kernel<<<dim3(NG / 4, HH), 128>>>();
    kda_scan_kernel<<<dim3(NCB, HH), 128>>>(out);
}

// round 11
// speedup vs baseline: 1.6616x; 1.4493x over previous
#include <cuda_runtime.h>
#include <cstdint>

#define TT 8192
#define HH 16
#define DD 128
#define HD (HH * DD)        // 2048
#define C3 (3 * HD)         // 6144
#define NCB 8               // column blocks per head
#define CPB 16              // columns per block
#define GS 8                // steps per smem stage = group size
#define NG (TT / GS)        // 1024 groups per head

typedef unsigned long long u64;

// ---------------- scratch (static device memory; no allocs allowed) --------
__device__ float g_q  [HH * TT * DD];   // [H][T][D]
__device__ float g_k  [HH * TT * DD];   // [H][T][D]
__device__ float g_dec[HH * TT * DD];   // [H][T][D]
__device__ float g_v  [HH * TT * DD];   // [H][T][D]
__device__ float g_KG [HH * TT * DD];   // [H][T][D] G_i∘k_i
__device__ float g_QG [HH * TT * DD];   // [H][T][D] G_i∘q_i
__device__ float g_KP [HH * TT * DD];   // [H][T][D] suffix-decayed keys
__device__ float g_G7 [HH * NG * DD];   // [H][NG][D] full-group decay
__device__ float g_b  [HH * TT];        // [H][T]
__device__ float g_c  [HH * NG * 128];  // [H][NG][128]: [0..64) solve C, [64..128) CQ

// ---------------- packed f32x2 helpers (sm_103a) ---------------------------
__device__ __forceinline__ u64 fma2(u64 a, u64 b, u64 c) {
    u64 d; asm("fma.rn.f32x2 %0, %1, %2, %3;" : "=l"(d) : "l"(a), "l"(b), "l"(c)); return d;
}
__device__ __forceinline__ u64 mul2(u64 a, u64 b) {
    u64 d; asm("mul.rn.f32x2 %0, %1, %2;" : "=l"(d) : "l"(a), "l"(b)); return d;
}
__device__ __forceinline__ float hsum2(u64 a) {
    float x, y; asm("mov.b64 {%0, %1}, %2;" : "=f"(x), "=f"(y) : "l"(a)); return x + y;
}
__device__ __forceinline__ u64 pack2(float x) {
    u64 d; asm("mov.b64 %0, {%1, %1};" : "=l"(d) : "f"(x)); return d;
}
__device__ __forceinline__ void cpa16(void* dst, const void* src) {
    unsigned d = (unsigned)__cvta_generic_to_shared(dst);
    asm volatile("cp.async.ca.shared.global [%0], [%1], 16;" :: "r"(d), "l"(src));
}
__device__ __forceinline__ float softplusf(float x) {
    return (x > 20.f) ? x : log1pf(expf(x));
}
__device__ __forceinline__ float dot4(float4 a, float4 b) {
    return a.x * b.x + a.y * b.y + a.z * b.z + a.w * b.w;
}

// ---------------- dummy kernel: shifts ncu's profiled slot onto the scan ---
__global__ void dummy_kernel() {}

// ============================================================================
// Phase 1: conv1d + SiLU, l2norm(q,k), gates  -> transposed [H][T][D] scratch
// ============================================================================
__global__ void prep_kernel(const float* __restrict__ xin,   // [T, 3HD]
                            const float* __restrict__ fg,    // [T, HD]
                            const float* __restrict__ beta,  // [T, H]
                            const float* __restrict__ cw,    // [3HD, 4]
                            const float* __restrict__ dtb,   // [H, D]
                            const float* __restrict__ alog)  // [H]
{
    const int t   = blockIdx.x;
    const int tid = threadIdx.x;                 // 256 threads

    __shared__ float sbuf[C3];
    __shared__ float snorm[32];
    __shared__ float snegA[HH];

    if (tid < HH) snegA[tid] = -expf(alog[tid]);

    const float4* x4  = (const float4*)xin;      // [T, 1536]
    const float4* w4  = (const float4*)cw;
    float4* sbuf4 = (float4*)sbuf;

    #pragma unroll
    for (int it = 0; it < 6; it++) {
        int c4 = tid + it * 256;                 // 0..1535
        float4 w0 = w4[c4 * 4 + 0];
        float4 w1 = w4[c4 * 4 + 1];
        float4 w2 = w4[c4 * 4 + 2];
        float4 w3 = w4[c4 * 4 + 3];
        float4 a0 = x4[(size_t)t * 1536 + c4];
        float4 acc;
        acc.x = a0.x * w0.w; acc.y = a0.y * w1.w;
        acc.z = a0.z * w2.w; acc.w = a0.w * w3.w;
        if (t >= 1) {
            float4 a = x4[(size_t)(t - 1) * 1536 + c4];
            acc.x += a.x * w0.z; acc.y += a.y * w1.z;
            acc.z += a.z * w2.z; acc.w += a.w * w3.z;
        }
        if (t >= 2) {
            float4 a = x4[(size_t)(t - 2) * 1536 + c4];
            acc.x += a.x * w0.y; acc.y += a.y * w1.y;
            acc.z += a.z * w2.y; acc.w += a.w * w3.y;
        }
        if (t >= 3) {
            float4 a = x4[(size_t)(t - 3) * 1536 + c4];
            acc.x += a.x * w0.x; acc.y += a.y * w1.x;
            acc.z += a.z * w2.x; acc.w += a.w * w3.x;
        }
        acc.x = acc.x / (1.f + expf(-acc.x));
        acc.y = acc.y / (1.f + expf(-acc.y));
        acc.z = acc.z / (1.f + expf(-acc.z));
        acc.w = acc.w / (1.f + expf(-acc.w));
        sbuf4[c4] = acc;
    }
    __syncthreads();

    const int wid = tid >> 5, lane = tid & 31;
    for (int g = wid; g < 32; g += 8) {
        const int base = g * 128;
        float v0 = sbuf[base + lane];
        float v1 = sbuf[base + 32 + lane];
        float v2 = sbuf[base + 64 + lane];
        float v3 = sbuf[base + 96 + lane];
        float ss = v0 * v0 + v1 * v1 + v2 * v2 + v3 * v3;
        #pragma unroll
        for (int off = 16; off > 0; off >>= 1)
            ss += __shfl_xor_sync(0xffffffffu, ss, off);
        if (lane == 0) snorm[g] = rsqrtf(ss + 1e-6f);
    }
    __syncthreads();

    const float qscale = 0.08838834764831845f;   // D^-0.5
    #pragma unroll
    for (int it = 0; it < 6; it++) {
        int c4 = tid + it * 256;
        int c  = c4 * 4;
        float4 val = sbuf4[c4];
        if (c < HD) {
            int h = c >> 7, d = c & 127;
            float sc = snorm[h] * qscale;
            val.x *= sc; val.y *= sc; val.z *= sc; val.w *= sc;
            ((float4*)g_q)[((size_t)h * TT + t) * 32 + (d >> 2)] = val;
        } else if (c < 2 * HD) {
            int cc = c - HD; int h = cc >> 7, d = cc & 127;
            float sc = snorm[16 + h];
            val.x *= sc; val.y *= sc; val.z *= sc; val.w *= sc;
            ((float4*)g_k)[((size_t)h * TT + t) * 32 + (d >> 2)] = val;
        } else {
            int cc = c - 2 * HD; int h = cc >> 7, d = cc & 127;
            ((float4*)g_v)[((size_t)h * TT + t) * 32 + (d >> 2)] = val;
        }
    }

    const float4* fg4  = (const float4*)fg;
    const float4* dtb4 = (const float4*)dtb;
    #pragma unroll
    for (int it = 0; it < 2; it++) {
        int c4 = tid + it * 256;                 // 0..511
        int h  = (c4 * 4) >> 7;
        float na = snegA[h];
        float4 gg = fg4[(size_t)t * 512 + c4];
        float4 bb = dtb4[c4];
        float4 r;
        r.x = expf(na * softplusf(gg.x + bb.x));
        r.y = expf(na * softplusf(gg.y + bb.y));
        r.z = expf(na * softplusf(gg.z + bb.z));
        r.w = expf(na * softplusf(gg.w + bb.w));
        ((float4*)g_dec)[((size_t)h * TT + t) * 32 + (((c4 * 4) & 127) >> 2)] = r;
    }
    if (tid < HH)
        g_b[tid * TT + t] = 1.f / (1.f + expf(-beta[(size_t)t * HH + tid]));
}

// ============================================================================
// Phase 1b: group operators + solve/output matrices. One warp per group.
// ============================================================================
__global__ void __launch_bounds__(128)
group_prep_kernel()
{
    const int h    = blockIdx.y;
    const int g    = blockIdx.x * 4 + (threadIdx.x >> 5);
    const int lane = threadIdx.x & 31;

    const size_t base = ((size_t)h * TT + (size_t)g * GS) * DD;
    const float4* kp4 = (const float4*)(g_k   + base);
    const float4* dp4 = (const float4*)(g_dec + base);
    const float4* qp4 = (const float4*)(g_q   + base);
    float4* KGout = (float4*)(g_KG + base);
    float4* QGout = (float4*)(g_QG + base);
    float4* KPout = (float4*)(g_KP + base);
    float4* G7out = (float4*)(g_G7 + ((size_t)h * NG + g) * DD);

    float4 dv[GS], kv[GS], qv[GS];
    #pragma unroll
    for (int i = 0; i < GS; i++) {
        dv[i] = dp4[i * 32 + lane];
        kv[i] = kp4[i * 32 + lane];
        qv[i] = qp4[i * 32 + lane];
    }

    // prefix decay products -> KG, QG, G7
    {
        float4 G = make_float4(1.f, 1.f, 1.f, 1.f);
        #pragma unroll
        for (int i = 0; i < GS; i++) {
            G.x *= dv[i].x; G.y *= dv[i].y; G.z *= dv[i].z; G.w *= dv[i].w;
            float4 o;
            o.x = G.x * kv[i].x; o.y = G.y * kv[i].y;
            o.z = G.z * kv[i].z; o.w = G.w * kv[i].w;
            KGout[i * 32 + lane] = o;
            o.x = G.x * qv[i].x; o.y = G.y * qv[i].y;
            o.z = G.z * qv[i].z; o.w = G.w * qv[i].w;
            QGout[i * 32 + lane] = o;
        }
        G7out[lane] = G;
    }

    float r[64];
    #pragma unroll
    for (int i = 0; i < GS; i++) r[i * 9] = dot4(qv[i], kv[i]);

    #pragma unroll
    for (int j = 0; j < GS; j++) {
        float4 w = kv[j];
        #pragma unroll
        for (int i = j + 1; i < GS; i++) {
            w.x *= dv[i].x; w.y *= dv[i].y; w.z *= dv[i].z; w.w *= dv[i].w;
            r[i * 8 + j] = dot4(kv[i], w);   // c_ij (lower)
            r[j * 8 + i] = dot4(qv[i], w);   // cq_ij (upper slot)
        }
        KPout[j * 32 + lane] = w;            // suffix-decayed key
    }

    #pragma unroll
    for (int off = 16; off > 0; off >>= 1) {
        #pragma unroll
        for (int m = 0; m < 64; m++)
            r[m] += __shfl_xor_sync(0xffffffffu, r[m], off);
    }
    if (lane == 0) {
        float* co = g_c + ((size_t)h * NG + g) * 128;
        // block 0: solve matrix (lower c_ij used; rest ignored)
        #pragma unroll
        for (int m = 0; m < 64; m++) co[m] = r[m];
        // block 1: CQ[i][j] = cq_ij (j<i), cq_ii (j==i), 0 (j>i)
        #pragma unroll
        for (int i = 0; i < GS; i++)
            #pragma unroll
            for (int j = 0; j < GS; j++)
                co[64 + i * 8 + j] = (j < i) ? r[j * 8 + i]
                                  : (j == i) ? r[i * 9] : 0.f;
    }
}

// ============================================================================
// Phase 2: 8-step-group scan, transposed layout.
// 128 thr: warp w owns cols [4w,4w+4); lane L owns D[4L,4L+4) (2 f32x2/col).
// cgrp = (L>>3)&3 selects the lane's solve column; myi = L&7 its output step.
// ============================================================================

// split-reduce stage: halves tracked set, partner offset o, new count n
#define RSTAGE_SPLIT(r, n, o) do {                                          \
    const bool _hi = (lane & (o)) != 0;                                     \
    _Pragma("unroll")                                                       \
    for (int _j = 0; _j < (n); _j++) {                                      \
        float _send = _hi ? r[_j] : r[_j + (n)];                            \
        float _recv = __shfl_xor_sync(0xffffffffu, _send, (o));             \
        r[_j] = (_hi ? r[_j + (n)] : r[_j]) + _recv;                        \
    }                                                                       \
} while (0)

#define PREFETCH(buf, t0) do {                                              \
    _Pragma("unroll")                                                       \
    for (int _j = 0; _j < 2; _j++) {                                        \
        int _c = tid + _j * 128;                                            \
        int _st = _c >> 5, _cc = _c & 31;                                   \
        size_t _go = (size_t)((t0) + _st) * DD + _cc * 4;                   \
        cpa16(&sKG[buf][_st][_cc], KGg + _go);                              \
        cpa16(&sQG[buf][_st][_cc], QGg + _go);                              \
        cpa16(&sKP[buf][_st][_cc], KPg + _go);                              \
    }                                                                       \
    if (tid < 32) {                                                         \
        int _st = tid >> 2, _part = tid & 3;                                \
        cpa16(&sv[buf][_st][_part * 4],                                     \
              vg + (size_t)((t0) + _st) * DD + _part * 4);                  \
    } else if (tid < 34) {                                                  \
        int _j2 = tid - 32;                                                 \
        cpa16(&sb[buf][_j2 * 4], bg + (t0) + _j2 * 4);                      \
    } else if (tid < 66) {                                                  \
        int _m = tid - 34;                                                  \
        cpa16(&sc[buf][_m * 4], cg + (size_t)((t0) >> 3) * 128 + _m * 4);   \
    } else if (tid < 98) {                                                  \
        int _cc = tid - 66;                                                 \
        cpa16(&sG7[buf][_cc], G7g + (size_t)((t0) >> 3) * DD + _cc * 4);    \
    }                                                                       \
} while (0)

__global__ void __launch_bounds__(128, 1)
kda_scan_kernel(float* __restrict__ out)
{
    __shared__ __align__(16) ulonglong2 sKG[2][GS][32];
    __shared__ __align__(16) ulonglong2 sQG[2][GS][32];
    __shared__ __align__(16) ulonglong2 sKP[2][GS][32];
    __shared__ __align__(16) ulonglong2 sG7[2][32];
    __shared__ __align__(16) float      sv[2][GS][16];
    __shared__ __align__(16) float      sb[2][GS];
    __shared__ __align__(16) float      sc[2][128];

    const int h    = blockIdx.y;
    const int cb   = blockIdx.x;
    const int tid  = threadIdx.x;
    const int lane = tid & 31;
    const int w    = tid >> 5;           // warp: columns [4w, 4w+4)
    const int cgrp = (lane >> 3) & 3;    // this lane's solve column (0..3)
    const int myi  = lane & 7;           // this lane's output step

    const size_t hbase = (size_t)h * TT * DD;
    const float* KGg = g_KG + hbase;
    const float* QGg = g_QG + hbase;
    const float* KPg = g_KP + hbase;
    const float* G7g = g_G7 + (size_t)h * NG * DD;
    const float* vg  = g_v  + hbase + cb * CPB;
    const float* bg  = g_b  + (size_t)h * TT;
    const float* cg  = g_c  + (size_t)h * NG * 128;
    const int colloc = 4 * w + cgrp;                    // column within block
    float* op = out + (size_t)h * DD + cb * CPB + colloc;  // + t*H*D per step

    // state: st[c][p] = S[D-slice pair p of lane][col 4w+c]
    u64 st[4][2];
    #pragma unroll
    for (int c = 0; c < 4; c++) { st[c][0] = 0ull; st[c][1] = 0ull; }

    PREFETCH(0, 0);
    asm volatile("cp.async.commit_group;" ::: "memory");
    PREFETCH(1, GS);
    asm volatile("cp.async.commit_group;" ::: "memory");

    #pragma unroll 1
    for (int t0 = 0; t0 < TT; t0 += GS) {
        const int buf = (t0 >> 3) & 1;
        asm volatile("cp.async.wait_group 1;" ::: "memory");
        __syncthreads();

        // ---- phase A: per-lane partial dots, r[8c+i]=km, x[8c+i]=o ----
        float r[32], x[32];
        #pragma unroll
        for (int i = 0; i < GS; i++) {
            ulonglong2 kg = sKG[buf][i][lane];
            #pragma unroll
            for (int c = 0; c < 4; c++) {
                u64 t = mul2(kg.x, st[c][0]);
                t = fma2(kg.y, st[c][1], t);
                r[8 * c + i] = hsum2(t);
            }
            ulonglong2 qg = sQG[buf][i][lane];
            #pragma unroll
            for (int c = 0; c < 4; c++) {
                u64 t = mul2(qg.x, st[c][0]);
                t = fma2(qg.y, st[c][1], t);
                x[8 * c + i] = hsum2(t);
            }
        }

        // ---- phase B: split stages (both), then km all-reduce + o split ----
        RSTAGE_SPLIT(r, 16, 16);  RSTAGE_SPLIT(x, 16, 16);
        RSTAGE_SPLIT(r,  8,  8);  RSTAGE_SPLIT(x,  8,  8);
        // km: all-reduce within 8-lane column group -> r[0..8) = km[i][cgrp]
        #pragma unroll
        for (int o = 4; o >= 1; o >>= 1) {
            #pragma unroll
            for (int j = 0; j < 8; j++)
                r[j] += __shfl_xor_sync(0xffffffffu, r[j], o);
        }
        // o: continue splitting -> x[0] = o[myi][cgrp]
        RSTAGE_SPLIT(x, 4, 4);
        RSTAGE_SPLIT(x, 2, 2);
        RSTAGE_SPLIT(x, 1, 1);

        // ---- phase C: triangular solve for column cgrp (redundant x8) ----
        float del[8];
        del[0] = sb[buf][0] * (sv[buf][0][colloc] - r[0]);
        #pragma unroll
        for (int i = 1; i < GS; i++) {
            float acc = r[i];
            #pragma unroll
            for (int j = 0; j < i; j++)
                acc = fmaf(sc[buf][i * 8 + j], del[j], acc);
            del[i] = sb[buf][i] * (sv[buf][i][colloc] - acc);
        }

        // ---- output: o[myi][cgrp] + sum_j CQ[myi][j]*del[j], one STG ----
        {
            const float* cqp = &sc[buf][64 + myi * 8];
            float oo = x[0];
            #pragma unroll
            for (int j = 0; j < GS; j++)
                oo = fmaf(cqp[j], del[j], oo);
            op[(size_t)(t0 + myi) * HD] = oo;
        }

        // ---- del broadcast across column groups + XOR permute ----
        float dc0[8], dc1[8], dc2[8], dc3[8];
        {
            const bool cg1 = (cgrp & 1) != 0;
            const bool cg2 = (cgrp & 2) != 0;
            #pragma unroll
            for (int i = 0; i < GS; i++) {
                float a = del[i];
                float b1 = __shfl_xor_sync(0xffffffffu, del[i], 8);   // cgrp^1
                float c2 = __shfl_xor_sync(0xffffffffu, del[i], 16);  // cgrp^2
                float d3 = __shfl_xor_sync(0xffffffffu, b1, 16);      // cgrp^3
                if (cg1) { float t = a; a = b1; b1 = t; t = c2; c2 = d3; d3 = t; }
                if (cg2) { float t = a; a = c2; c2 = t; t = b1; b1 = d3; d3 = t; }
                dc0[i] = a; dc1[i] = b1; dc2[i] = c2; dc3[i] = d3;
            }
        }

        // ---- phase D: state update st = G7∘st + sum_i KP_i * del_i ----
        {
            ulonglong2 g7 = sG7[buf][lane];
            #pragma unroll
            for (int c = 0; c < 4; c++) {
                st[c][0] = mul2(g7.x, st[c][0]);
                st[c][1] = mul2(g7.y, st[c][1]);
            }
        }
        #pragma unroll
        for (int i = 0; i < GS; i++) {
            ulonglong2 kp = sKP[buf][i][lane];
            u64 d0 = pack2(dc0[i]), d1 = pack2(dc1[i]);
            u64 d2 = pack2(dc2[i]), d3 = pack2(dc3[i]);
            st[0][0] = fma2(kp.x, d0, st[0][0]); st[0][1] = fma2(kp.y, d0, st[0][1]);
            st[1][0] = fma2(kp.x, d1, st[1][0]); st[1][1] = fma2(kp.y, d1, st[1][1]);
            st[2][0] = fma2(kp.x, d2, st[2][0]); st[2][1] = fma2(kp.y, d2, st[2][1]);
            st[3][0] = fma2(kp.x, d3, st[3][0]); st[3][1] = fma2(kp.y, d3, st[3][1]);
        }

        __syncthreads();
        if (t0 + 2 * GS < TT) {
            PREFETCH(buf, t0 + 2 * GS);
        }
        asm volatile("cp.async.commit_group;" ::: "memory");
    }
}

// ============================================================================
extern "C" void kernel_launch(void* const* d_in, const int* in_sizes, int n_in,
                              void* d_out, int out_size)
{
    const float* mixed = (const float*)d_in[0];   // [T, 3HD]
    const float* fg    = (const float*)d_in[1];   // [T, HD]
    const float* beta  = (const float*)d_in[2];   // [T, H]
    const float* cw    = (const float*)d_in[3];   // [3HD, 4]
    const float* dtb   = (const float*)d_in[4];   // [H, D]
    const float* alog  = (const float*)d_in[5];   // [H]
    float* out = (float*)d_out;                   // [T, H, D] f32

    dummy_kernel<<<1, 32>>>();                    // keeps ncu slot on the scan
    prep_kernel<<<TT, 256>>>(mixed, fg, beta, cw, dtb, alog);
    group_prep_kernel<<<dim3(NG / 4, HH), 128>>>();
    kda_scan_kernel<<<dim3(NCB, HH), 128>>>(out);
}